// round 8
// baseline (speedup 1.0000x reference)
#include <cuda_runtime.h>
#include <cuda_bf16.h>
#include <cstdint>

// Problem constants
#define B_     64
#define H_     512
#define W_     512
#define C_     3
#define G_     64
#define K_     3
#define D_IN   (K_*G_*G_*C_)   // 36864
#define HG_    128
#define HL_    128

// GEMM split-K config
#define NCHUNK 144
#define DC     256             // K-dims per CTA chunk (NCHUNK*DC == D_IN)

// Scratch (device globals): phi as split bf16 hi/lo (compensated GEMM inputs)
__device__ __nv_bfloat16 g_phiH[(size_t)B_ * D_IN];   // 4.7 MB
__device__ __nv_bfloat16 g_phiL[(size_t)B_ * D_IN];   // 4.7 MB
__device__ float g_part[(size_t)NCHUNK * B_ * HG_];   // 4.7 MB

__device__ __forceinline__ uint32_t smem_u32(const void* p) {
    uint32_t a;
    asm("{ .reg .u64 t; cvta.to.shared.u64 t, %1; cvt.u32.u64 %0, t; }"
        : "=r"(a) : "l"(p));
    return a;
}
__device__ __forceinline__ void cp16(uint32_t dst, const void* src) {
    asm volatile("cp.async.cg.shared.global [%0], [%1], 16;"
                 :: "r"(dst), "l"(src) : "memory");
}
#define CP_COMMIT() asm volatile("cp.async.commit_group;" ::: "memory")
#define CP_WAIT0()  asm volatile("cp.async.wait_group 0;" ::: "memory")

__device__ __forceinline__ void store_phi(size_t off, float v) {
    __nv_bfloat16 h = __float2bfloat16(v);
    __nv_bfloat16 e = __float2bfloat16(v - __bfloat162float(h));
    g_phiH[off] = h;
    g_phiL[off] = e;
}

// ---------------------------------------------------------------------------
// Kernel 1: fused multi-scale glimpse extraction + avg pooling (v5: cp.async)
//
// One CTA per (gy2 pair gp, b): stages the 8 source rows covering two k=2
// output rows via cp.async 16B (interior), scalar fallback at window edges,
// zeros outside the image. Then derives k=2 (4x4 pool), k=1 (2x2 pool,
// central cols), k=0 (copy, central cols) and writes phi as bf16 hi/lo.
// ---------------------------------------------------------------------------
#define BUFSTR 776   // floats per staged row (772 used + pad)

__global__ __launch_bounds__(256) void extract_kernel(
    const float* __restrict__ x, const float* __restrict__ l)
{
    __shared__ float buf[8 * BUFSTR];          // 24.8 KB
    const uint32_t sbuf = smem_u32(buf);

    const int gp  = blockIdx.x;                // 0..31 (two gy2 rows each)
    const int b   = blockIdx.y;
    const int tid = threadIdx.x;

    // denormalize coords exactly like reference: trunc((0.5*(l+1))*512)
    const float lx = __ldg(&l[b * 2 + 0]);
    const float ly = __ldg(&l[b * 2 + 1]);
    const int cx = (int)((0.5f * (lx + 1.0f)) * 512.0f);
    const int cy = (int)((0.5f * (ly + 1.0f)) * 512.0f);
    const int xs  = cx - 128;
    const int ys0 = cy - 128 + gp * 8;         // first of 8 staged rows

    const int jlo = (xs < 0 ? -xs : 0) * 3;
    const int xe  = xs + 256;
    const int jhi = ((xe > W_ ? W_ : xe) - xs) * 3;
    const int s   = (xs * 3) & 3;              // uniform element shift

    // stage 8 contiguous source rows
    #pragma unroll
    for (int rr = 0; rr < 8; rr++) {
        const int y = ys0 + rr;
        const bool yok = (y >= 0) && (y < H_);
        const float* rowp = x + (((size_t)b * H_ + y) * W_ + xs) * C_;
        const uint32_t dstRow = sbuf + (rr * BUFSTR) * 4;
        if (tid < 193) {
            const int i  = tid;
            const int e0 = 4 * i - s;
            if (yok && e0 >= jlo && e0 + 3 < jhi) {
                cp16(dstRow + 16 * i, rowp + e0);          // aligned 16B
            } else {
                float4 v = make_float4(0.f, 0.f, 0.f, 0.f);
                if (yok && e0 + 3 >= jlo && e0 < jhi) {
                    float* vp = &v.x;
                    #pragma unroll
                    for (int t = 0; t < 4; t++) {
                        const int e = e0 + t;
                        if (e >= jlo && e < jhi) vp[t] = __ldg(rowp + e);
                    }
                }
                *reinterpret_cast<float4*>(&buf[rr * BUFSTR + 4 * i]) = v;
            }
        }
    }
    CP_COMMIT();
    CP_WAIT0();
    __syncthreads();

    if (tid < 192) {
        const int gx = tid / 3;
        const int c  = tid - gx * 3;
        const float* bufS = buf + s;
        const size_t phiB = (size_t)b * D_IN;

        #pragma unroll
        for (int g = 0; g < 2; g++) {
            const int gy2 = 2 * gp + g;
            const int r0  = g * 4;             // staged row base for this gy2

            // ---- k=2: pool 4x4 ----
            {
                float sum = 0.0f;
                #pragma unroll
                for (int dy = 0; dy < 4; dy++)
                    #pragma unroll
                    for (int dx = 0; dx < 4; dx++)
                        sum += bufS[(r0 + dy) * BUFSTR + (gx * 4 + dx) * 3 + c];
                store_phi(phiB + (2 * G_ + gy2) * (G_ * C_) + tid, sum * (1.0f / 16.0f));
            }

            // ---- k=1: two rows, pool 2x2 over central 128 cols ----
            if (gy2 >= 16 && gy2 < 48) {
                #pragma unroll
                for (int h = 0; h < 2; h++) {
                    const int gy1 = 2 * gy2 - 32 + h;
                    float sum = 0.0f;
                    #pragma unroll
                    for (int dy = 0; dy < 2; dy++)
                        #pragma unroll
                        for (int dx = 0; dx < 2; dx++)
                            sum += bufS[(r0 + 2 * h + dy) * BUFSTR + (64 + gx * 2 + dx) * 3 + c];
                    store_phi(phiB + (G_ + gy1) * (G_ * C_) + tid, sum * 0.25f);
                }
            }

            // ---- k=0: four rows, direct copy of central 64 cols ----
            if (gy2 >= 24 && gy2 < 40) {
                #pragma unroll
                for (int rr = 0; rr < 4; rr++) {
                    const int gy0 = 4 * gy2 - 96 + rr;
                    store_phi(phiB + gy0 * (G_ * C_) + tid,
                              bufS[(r0 + rr) * BUFSTR + (96 + gx) * 3 + c]);
                }
            }
        }
    }
}

// ---------------------------------------------------------------------------
// Kernel 2: split-K GEMM via mma.sync bf16, bf16x3 compensated split.
// Grid 144, 512 threads. DC=256 as 2 slabs of 128.
// A tiles filled by pure cp.async from g_phiH/L (double-buffered per slab).
// W1 slab staged raw fp32 via cp.async; slab1 loads issued before slab0
// compute (latency hidden). B converted hi/lo from staging in smem.
// ---------------------------------------------------------------------------
#define KSTR    136                      // padded K stride in bf16 (272B rows)
#define A_TILE  (64 * KSTR * 2)          // 17408 B
#define B_TILE  (128 * KSTR * 2)         // 34816 B
#define OFF_A   0                        // 4 A tiles: [slab][H/L]
#define OFF_BH  (4 * A_TILE)             // 69632
#define OFF_BL  (OFF_BH + B_TILE)        // 104448
#define OFF_STG (OFF_BL + B_TILE)        // 139264, raw W1 slab fp32
#define SMEM_GEMM (OFF_STG + 128 * 128 * 4)  // 204800 B

__device__ __forceinline__ void ldsm_x4(uint32_t a[4], uint32_t addr) {
    asm volatile("ldmatrix.sync.aligned.m8n8.x4.shared.b16 {%0,%1,%2,%3}, [%4];"
                 : "=r"(a[0]), "=r"(a[1]), "=r"(a[2]), "=r"(a[3]) : "r"(addr));
}
__device__ __forceinline__ void mma_bf16(
    float c[4], const uint32_t a[4], uint32_t b0, uint32_t b1)
{
    asm volatile(
        "mma.sync.aligned.m16n8k16.row.col.f32.bf16.bf16.f32 "
        "{%0,%1,%2,%3}, {%4,%5,%6,%7}, {%8,%9}, {%0,%1,%2,%3};"
        : "+f"(c[0]), "+f"(c[1]), "+f"(c[2]), "+f"(c[3])
        : "r"(a[0]), "r"(a[1]), "r"(a[2]), "r"(a[3]), "r"(b0), "r"(b1));
}
__device__ __forceinline__ uint32_t hi_lo_pack(float v0, float v1, uint32_t& lo_out)
{
    __nv_bfloat16 h0 = __float2bfloat16(v0);
    __nv_bfloat16 h1 = __float2bfloat16(v1);
    __nv_bfloat16 e0 = __float2bfloat16(v0 - __bfloat162float(h0));
    __nv_bfloat16 e1 = __float2bfloat16(v1 - __bfloat162float(h1));
    __nv_bfloat162 hp; hp.x = h0; hp.y = h1;
    __nv_bfloat162 lp; lp.x = e0; lp.y = e1;
    lo_out = *reinterpret_cast<uint32_t*>(&lp);
    return *reinterpret_cast<uint32_t*>(&hp);
}

__global__ __launch_bounds__(512) void gemm_mma_kernel(const float* __restrict__ W1)
{
    extern __shared__ char smem[];
    const uint32_t sb = smem_u32(smem);
    const int tid  = threadIdx.x;
    const int wid  = tid >> 5;
    const int lane = tid & 31;

    // warp tiling: mt = wid>>2 (m16 tiles), nq = wid&3 (n32 quarters)
    const int mt = wid >> 2;
    const int nq = wid & 3;

    const uint32_t aRel = (uint32_t)((mt * 16 + (lane & 15)) * (KSTR * 2)
                                     + (lane >> 4) * 16);
    const uint32_t bRel = (uint32_t)((nq * 32 + ((lane >> 4) * 8) + (lane & 7)) * (KSTR * 2)
                                     + (((lane >> 3) & 1) * 16));

    // ---- helpers as lambdas ----
    auto fillA = [&](int slab, int d0) {
        const uint32_t base = sb + OFF_A + slab * 2 * A_TILE;
        for (int idx = tid; idx < 64 * 16; idx += 512) {
            const int m = idx >> 4;
            const int i = idx & 15;
            const uint32_t dst = base + m * (KSTR * 2) + i * 16;
            const size_t src = (size_t)m * D_IN + d0 + i * 8;
            cp16(dst,          &g_phiH[src]);
            cp16(dst + A_TILE, &g_phiL[src]);
        }
    };
    auto stageW1 = [&](int d0) {
        for (int idx = tid; idx < 128 * 32; idx += 512) {
            const int r = idx >> 5;
            const int i = idx & 31;
            cp16(sb + OFF_STG + r * 512 + i * 16, &W1[(size_t)(d0 + r) * HG_ + i * 4]);
        }
    };
    auto convB = [&]() {
        const float* stg = reinterpret_cast<const float*>(smem + OFF_STG);
        for (int idx = tid; idx < 64 * 128; idx += 512) {
            const int kk = idx >> 7;
            const int n  = idx & 127;
            const float v0 = stg[(2 * kk)     * 128 + n];
            const float v1 = stg[(2 * kk + 1) * 128 + n];
            uint32_t lo, hi = hi_lo_pack(v0, v1, lo);
            const int off = n * (KSTR * 2) + kk * 4;
            *reinterpret_cast<uint32_t*>(smem + OFF_BH + off) = hi;
            *reinterpret_cast<uint32_t*>(smem + OFF_BL + off) = lo;
        }
    };

    float acc[4][4];
    #pragma unroll
    for (int nt = 0; nt < 4; nt++)
        #pragma unroll
        for (int j = 0; j < 4; j++) acc[nt][j] = 0.0f;

    auto compute = [&](int slab) {
        #pragma unroll
        for (int pass = 0; pass < 3; pass++) {
            const uint32_t aBase = sb + OFF_A + slab * 2 * A_TILE
                                   + ((pass == 2) ? A_TILE : 0) + aRel;
            const uint32_t bBase = sb + ((pass == 1) ? OFF_BL : OFF_BH) + bRel;
            #pragma unroll
            for (int kt = 0; kt < 8; kt++) {
                uint32_t a[4];
                ldsm_x4(a, aBase + kt * 32);
                #pragma unroll
                for (int np = 0; np < 2; np++) {
                    uint32_t bq[4];
                    ldsm_x4(bq, bBase + np * 16 * (KSTR * 2) + kt * 32);
                    mma_bf16(acc[np * 2 + 0], a, bq[0], bq[1]);
                    mma_bf16(acc[np * 2 + 1], a, bq[2], bq[3]);
                }
            }
        }
    };

    const int d0 = blockIdx.x * DC;

    // prologue: slab0 A + W1 raw
    fillA(0, d0);
    stageW1(d0);
    CP_COMMIT();
    CP_WAIT0();
    __syncthreads();

    convB();                       // slab0 B from staging
    __syncthreads();               // staging free, B ready

    // prefetch slab1 while computing slab0
    fillA(1, d0 + 128);
    stageW1(d0 + 128);
    CP_COMMIT();

    compute(0);

    CP_WAIT0();
    __syncthreads();               // compute0 done reading B; slab1 raw arrived
    convB();                       // slab1 B
    __syncthreads();

    compute(1);

    // ---- epilogue: write 64x128 partial tile ----
    float* part = &g_part[(size_t)blockIdx.x * (B_ * HG_)];
    const int qid = lane >> 2;
    const int tq  = lane & 3;
    const int row0 = mt * 16 + qid;
    #pragma unroll
    for (int nt = 0; nt < 4; nt++) {
        const int col = nq * 32 + nt * 8 + tq * 2;
        float2 v0; v0.x = acc[nt][0]; v0.y = acc[nt][1];
        float2 v1; v1.x = acc[nt][2]; v1.y = acc[nt][3];
        *reinterpret_cast<float2*>(part + row0 * HG_ + col) = v0;
        *reinterpret_cast<float2*>(part + (row0 + 8) * HG_ + col) = v1;
    }
}

// ---------------------------------------------------------------------------
// Kernel 3: reduce partials + bias + relu + l-branch.
// ---------------------------------------------------------------------------
__global__ __launch_bounds__(512) void finalize_kernel(
    const float* __restrict__ l, const float* __restrict__ b1,
    const float* __restrict__ W2, const float* __restrict__ b2,
    float* __restrict__ out)
{
    __shared__ float red[4][HG_];
    const int b = blockIdx.x;
    const int tid = threadIdx.x;
    const int h = tid & 127;
    const int p = tid >> 7;

    float s = 0.0f;
    #pragma unroll 9
    for (int c = p; c < NCHUNK; c += 4)
        s += g_part[(size_t)c * (B_ * HG_) + b * HG_ + h];
    red[p][h] = s;
    __syncthreads();

    if (p == 0) {
        const float v = red[0][h] + red[1][h] + red[2][h] + red[3][h] + b1[h];
        out[b * (HG_ + HL_) + h] = fmaxf(v, 0.0f);
        const float lw = l[b * 2 + 0] * W2[h] + l[b * 2 + 1] * W2[HL_ + h] + b2[h];
        out[b * (HG_ + HL_) + HG_ + h] = fmaxf(lw, 0.0f);
    }
}

// ---------------------------------------------------------------------------
extern "C" void kernel_launch(void* const* d_in, const int* in_sizes, int n_in,
                              void* d_out, int out_size)
{
    const float* x  = (const float*)d_in[0];
    const float* l  = (const float*)d_in[1];
    const float* W1 = (const float*)d_in[2];
    const float* b1 = (const float*)d_in[3];
    const float* W2 = (const float*)d_in[4];
    const float* b2 = (const float*)d_in[5];
    float* out = (float*)d_out;

    static bool attr_set = false;
    if (!attr_set) {
        cudaFuncSetAttribute(gemm_mma_kernel,
                             cudaFuncAttributeMaxDynamicSharedMemorySize, SMEM_GEMM);
        attr_set = true;
    }

    dim3 eg(32, B_);
    extract_kernel<<<eg, 256>>>(x, l);
    gemm_mma_kernel<<<NCHUNK, 512, SMEM_GEMM>>>(W1);
    finalize_kernel<<<B_, 512>>>(l, b1, W2, b2, out);
}

// round 9
// speedup vs baseline: 1.3835x; 1.3835x over previous
#include <cuda_runtime.h>
#include <cuda_bf16.h>
#include <cstdint>

// Problem constants
#define B_     64
#define H_     512
#define W_     512
#define C_     3
#define G_     64
#define K_     3
#define D_IN   (K_*G_*G_*C_)   // 36864
#define HG_    128
#define HL_    128

// GEMM split-K config
#define NCHUNK 144
#define DC     256             // K-dims per CTA chunk (NCHUNK*DC == D_IN)

// Scratch (device globals): phi as split bf16 hi/lo (compensated GEMM inputs)
__device__ __nv_bfloat16 g_phiH[(size_t)B_ * D_IN];   // 4.7 MB
__device__ __nv_bfloat16 g_phiL[(size_t)B_ * D_IN];   // 4.7 MB
__device__ float g_part[(size_t)NCHUNK * B_ * HG_];   // 4.7 MB

__device__ __forceinline__ uint32_t smem_u32(const void* p) {
    uint32_t a;
    asm("{ .reg .u64 t; cvta.to.shared.u64 t, %1; cvt.u32.u64 %0, t; }"
        : "=r"(a) : "l"(p));
    return a;
}

__device__ __forceinline__ void store_phi(size_t off, float v) {
    __nv_bfloat16 h = __float2bfloat16(v);
    __nv_bfloat16 e = __float2bfloat16(v - __bfloat162float(h));
    g_phiH[off] = h;
    g_phiL[off] = e;
}

// ---------------------------------------------------------------------------
// Kernel 1: fused multi-scale glimpse extraction + avg pooling
// (R6 structure — measured best at 13.2us — with bf16 hi/lo phi output)
//
// One CTA per (gy2 in [0,64), b). Stages the 4 source rows of the k=2 window
// (768 floats each) with scalar predicated loads (L1-friendly), then derives:
//   k=2: 4x4 pool; k=1 (gy2 in [16,48)): 2x2 pool central; k=0 ([24,40)): copy.
// ---------------------------------------------------------------------------
__global__ __launch_bounds__(192) void extract_kernel(
    const float* __restrict__ x, const float* __restrict__ l)
{
    __shared__ float buf[4 * 768];

    const int gy2 = blockIdx.x;
    const int b   = blockIdx.y;
    const int tid = threadIdx.x;

    // denormalize coords exactly like reference: trunc((0.5*(l+1))*512)
    const float lx = __ldg(&l[b * 2 + 0]);
    const float ly = __ldg(&l[b * 2 + 1]);
    const int cx = (int)((0.5f * (lx + 1.0f)) * 512.0f);
    const int cy = (int)((0.5f * (ly + 1.0f)) * 512.0f);
    const int xs = cx - 128;
    const int ys = cy - 128 + gy2 * 4;

    const int jlo = (xs < 0 ? -xs : 0) * 3;
    const int xe  = xs + 256;
    const int jhi = ((xe > W_ ? W_ : xe) - xs) * 3;

    // stage 4 contiguous source rows (zero-filled OOB), scalar loads
    #pragma unroll
    for (int rr = 0; rr < 4; rr++) {
        const int y = ys + rr;
        const bool yok = (y >= 0) && (y < H_);
        const float* rowp = x + (((size_t)b * H_ + y) * W_ + xs) * C_;
        #pragma unroll
        for (int it = 0; it < 4; it++) {
            const int j = tid + it * 192;
            float v = 0.0f;
            if (yok && j >= jlo && j < jhi) v = __ldg(rowp + j);
            buf[rr * 768 + j] = v;
        }
    }
    __syncthreads();

    const int gx = tid / 3;
    const int c  = tid - gx * 3;
    const size_t phiB = (size_t)b * D_IN;

    // ---- k=2: pool 4x4 ----
    {
        float sum = 0.0f;
        #pragma unroll
        for (int dy = 0; dy < 4; dy++)
            #pragma unroll
            for (int dx = 0; dx < 4; dx++)
                sum += buf[dy * 768 + (gx * 4 + dx) * 3 + c];
        store_phi(phiB + (2 * G_ + gy2) * (G_ * C_) + tid, sum * (1.0f / 16.0f));
    }

    // ---- k=1: two output rows, pool 2x2 over central 128 cols ----
    if (gy2 >= 16 && gy2 < 48) {
        #pragma unroll
        for (int h = 0; h < 2; h++) {
            const int gy1 = 2 * gy2 - 32 + h;
            float sum = 0.0f;
            #pragma unroll
            for (int dy = 0; dy < 2; dy++)
                #pragma unroll
                for (int dx = 0; dx < 2; dx++)
                    sum += buf[(2 * h + dy) * 768 + (64 + gx * 2 + dx) * 3 + c];
            store_phi(phiB + (G_ + gy1) * (G_ * C_) + tid, sum * 0.25f);
        }
    }

    // ---- k=0: four output rows, direct copy of central 64 cols ----
    if (gy2 >= 24 && gy2 < 40) {
        #pragma unroll
        for (int rr = 0; rr < 4; rr++) {
            const int gy0 = 4 * gy2 - 96 + rr;
            store_phi(phiB + gy0 * (G_ * C_) + tid, buf[rr * 768 + (96 + gx) * 3 + c]);
        }
    }
}

// ---------------------------------------------------------------------------
// Kernel 2: split-K GEMM via mma.sync bf16 (R7 structure — measured best),
// bf16x3 compensated: D = Ah*Bh + Ah*Bl + Al*Bh, fp32 accumulate.
// Grid 144, 512 threads (16 warps, warp = 16m x 32n). DC=256 as 2 slabs.
// A tiles copied directly from bf16 g_phiH/L (16B vector loads, no convert).
// ---------------------------------------------------------------------------
#define KSTR   136                       // padded K stride in bf16 (272B rows)
#define A_TILE (64 * KSTR * 2)           // 17408 B
#define B_TILE (128 * KSTR * 2)          // 34816 B
#define OFF_AH 0
#define OFF_AL A_TILE
#define OFF_BH (2 * A_TILE)
#define OFF_BL (2 * A_TILE + B_TILE)
#define SMEM_GEMM (2 * A_TILE + 2 * B_TILE)   // 104448 B

__device__ __forceinline__ void ldsm_x4(uint32_t a[4], uint32_t addr) {
    asm volatile("ldmatrix.sync.aligned.m8n8.x4.shared.b16 {%0,%1,%2,%3}, [%4];"
                 : "=r"(a[0]), "=r"(a[1]), "=r"(a[2]), "=r"(a[3]) : "r"(addr));
}
__device__ __forceinline__ void mma_bf16(
    float c[4], const uint32_t a[4], uint32_t b0, uint32_t b1)
{
    asm volatile(
        "mma.sync.aligned.m16n8k16.row.col.f32.bf16.bf16.f32 "
        "{%0,%1,%2,%3}, {%4,%5,%6,%7}, {%8,%9}, {%0,%1,%2,%3};"
        : "+f"(c[0]), "+f"(c[1]), "+f"(c[2]), "+f"(c[3])
        : "r"(a[0]), "r"(a[1]), "r"(a[2]), "r"(a[3]), "r"(b0), "r"(b1));
}
__device__ __forceinline__ uint32_t hi_lo_pack(float v0, float v1, uint32_t& lo_out)
{
    __nv_bfloat16 h0 = __float2bfloat16(v0);
    __nv_bfloat16 h1 = __float2bfloat16(v1);
    __nv_bfloat16 e0 = __float2bfloat16(v0 - __bfloat162float(h0));
    __nv_bfloat16 e1 = __float2bfloat16(v1 - __bfloat162float(h1));
    __nv_bfloat162 hp; hp.x = h0; hp.y = h1;
    __nv_bfloat162 lp; lp.x = e0; lp.y = e1;
    lo_out = *reinterpret_cast<uint32_t*>(&lp);
    return *reinterpret_cast<uint32_t*>(&hp);
}

__global__ __launch_bounds__(512) void gemm_mma_kernel(const float* __restrict__ W1)
{
    extern __shared__ char smem[];
    const uint32_t sb = smem_u32(smem);
    const int tid  = threadIdx.x;
    const int wid  = tid >> 5;
    const int lane = tid & 31;

    // warp tiling: mt = wid>>2 (m16 tiles 0..3), nq = wid&3 (n32 quarters)
    const int mt = wid >> 2;
    const int nq = wid & 3;

    const uint32_t aRel = (uint32_t)((mt * 16 + (lane & 15)) * (KSTR * 2)
                                     + (lane >> 4) * 16);
    const uint32_t bRel = (uint32_t)((nq * 32 + ((lane >> 4) * 8) + (lane & 7)) * (KSTR * 2)
                                     + (((lane >> 3) & 1) * 16));

    float acc[4][4];
    #pragma unroll
    for (int nt = 0; nt < 4; nt++)
        #pragma unroll
        for (int j = 0; j < 4; j++) acc[nt][j] = 0.0f;

    for (int slab = 0; slab < 2; slab++) {
        const int d0 = blockIdx.x * DC + slab * 128;

        if (slab) __syncthreads();   // protect smem reuse

        // ---- fill A (64 x 128 bf16) hi/lo: straight 16B copies ----
        for (int idx = tid; idx < 64 * 16; idx += 512) {
            const int m = idx >> 4;
            const int i = idx & 15;                    // 16B chunk (8 bf16)
            const size_t src = (size_t)m * D_IN + d0 + i * 8;
            const int off = m * (KSTR * 2) + i * 16;
            *reinterpret_cast<uint4*>(smem + OFF_AH + off) =
                *reinterpret_cast<const uint4*>(&g_phiH[src]);
            *reinterpret_cast<uint4*>(smem + OFF_AL + off) =
                *reinterpret_cast<const uint4*>(&g_phiL[src]);
        }

        // ---- fill B^T (128 n x 128 k): B[n][k] = W1[d0+k][n], hi/lo ----
        for (int idx = tid; idx < 64 * 128; idx += 512) {
            const int kk = idx >> 7;
            const int n  = idx & 127;
            const float v0 = __ldg(&W1[(size_t)(d0 + 2 * kk)     * HG_ + n]);
            const float v1 = __ldg(&W1[(size_t)(d0 + 2 * kk + 1) * HG_ + n]);
            uint32_t lo, hi = hi_lo_pack(v0, v1, lo);
            const int off = n * (KSTR * 2) + kk * 4;
            *reinterpret_cast<uint32_t*>(smem + OFF_BH + off) = hi;
            *reinterpret_cast<uint32_t*>(smem + OFF_BL + off) = lo;
        }
        __syncthreads();

        // ---- 3 compensated passes over this slab ----
        #pragma unroll
        for (int pass = 0; pass < 3; pass++) {
            const uint32_t aBase = sb + ((pass == 2) ? OFF_AL : OFF_AH) + aRel;
            const uint32_t bBase = sb + ((pass == 1) ? OFF_BL : OFF_BH) + bRel;
            #pragma unroll
            for (int kt = 0; kt < 8; kt++) {
                uint32_t a[4];
                ldsm_x4(a, aBase + kt * 32);
                #pragma unroll
                for (int np = 0; np < 2; np++) {
                    uint32_t bq[4];
                    ldsm_x4(bq, bBase + np * 16 * (KSTR * 2) + kt * 32);
                    mma_bf16(acc[np * 2 + 0], a, bq[0], bq[1]);
                    mma_bf16(acc[np * 2 + 1], a, bq[2], bq[3]);
                }
            }
        }
    }

    // ---- epilogue: write 64x128 partial tile ----
    float* part = &g_part[(size_t)blockIdx.x * (B_ * HG_)];
    const int qid = lane >> 2;
    const int tq  = lane & 3;
    const int row0 = mt * 16 + qid;
    #pragma unroll
    for (int nt = 0; nt < 4; nt++) {
        const int col = nq * 32 + nt * 8 + tq * 2;
        float2 v0; v0.x = acc[nt][0]; v0.y = acc[nt][1];
        float2 v1; v1.x = acc[nt][2]; v1.y = acc[nt][3];
        *reinterpret_cast<float2*>(part + row0 * HG_ + col) = v0;
        *reinterpret_cast<float2*>(part + (row0 + 8) * HG_ + col) = v1;
    }
}

// ---------------------------------------------------------------------------
// Kernel 3: reduce partials + bias + relu + l-branch.
// ---------------------------------------------------------------------------
__global__ __launch_bounds__(512) void finalize_kernel(
    const float* __restrict__ l, const float* __restrict__ b1,
    const float* __restrict__ W2, const float* __restrict__ b2,
    float* __restrict__ out)
{
    __shared__ float red[4][HG_];
    const int b = blockIdx.x;
    const int tid = threadIdx.x;
    const int h = tid & 127;
    const int p = tid >> 7;

    float s = 0.0f;
    #pragma unroll 9
    for (int c = p; c < NCHUNK; c += 4)
        s += g_part[(size_t)c * (B_ * HG_) + b * HG_ + h];
    red[p][h] = s;
    __syncthreads();

    if (p == 0) {
        const float v = red[0][h] + red[1][h] + red[2][h] + red[3][h] + b1[h];
        out[b * (HG_ + HL_) + h] = fmaxf(v, 0.0f);
        const float lw = l[b * 2 + 0] * W2[h] + l[b * 2 + 1] * W2[HL_ + h] + b2[h];
        out[b * (HG_ + HL_) + HG_ + h] = fmaxf(lw, 0.0f);
    }
}

// ---------------------------------------------------------------------------
extern "C" void kernel_launch(void* const* d_in, const int* in_sizes, int n_in,
                              void* d_out, int out_size)
{
    const float* x  = (const float*)d_in[0];
    const float* l  = (const float*)d_in[1];
    const float* W1 = (const float*)d_in[2];
    const float* b1 = (const float*)d_in[3];
    const float* W2 = (const float*)d_in[4];
    const float* b2 = (const float*)d_in[5];
    float* out = (float*)d_out;

    static bool attr_set = false;
    if (!attr_set) {
        cudaFuncSetAttribute(gemm_mma_kernel,
                             cudaFuncAttributeMaxDynamicSharedMemorySize, SMEM_GEMM);
        attr_set = true;
    }

    dim3 eg(G_, B_);
    extract_kernel<<<eg, 192>>>(x, l);
    gemm_mma_kernel<<<NCHUNK, 512, SMEM_GEMM>>>(W1);
    finalize_kernel<<<B_, 512>>>(l, b1, W2, b2, out);
}